// round 13
// baseline (speedup 1.0000x reference)
#include <cuda_runtime.h>
#include <math.h>

#define BB   4
#define SS   4096
#define QEPS 1e-6f

typedef unsigned long long u64;

// ---- scratch (no allocation allowed): K1 -> K2 hand-off ----
__device__ __align__(16) float g_rmx[BB * SS];
__device__ __align__(16) float g_rmy[BB * SS];
__device__ __align__(16) float g_k1x[BB * SS];
__device__ __align__(16) float g_k1y[BB * SS];
__device__ __align__(16) float g_inv[BB * SS];
__device__ __align__(16) float g_rowsum[BB * SS];

// ---- packed fp32x2 helpers (Blackwell FFMA2 pipe, PTX-only) ----
__device__ __forceinline__ u64 f2_mul(u64 a, u64 b) {
    u64 r; asm("mul.rn.f32x2 %0, %1, %2;" : "=l"(r) : "l"(a), "l"(b)); return r;
}
__device__ __forceinline__ u64 f2_fma(u64 a, u64 b, u64 c) {
    u64 r; asm("fma.rn.f32x2 %0, %1, %2, %3;" : "=l"(r) : "l"(a), "l"(b), "l"(c)); return r;
}
__device__ __forceinline__ u64 f2_add(u64 a, u64 b) {
    u64 r; asm("add.rn.f32x2 %0, %1, %2;" : "=l"(r) : "l"(a), "l"(b)); return r;
}
__device__ __forceinline__ u64 pack2(float lo, float hi) {
    u64 r; asm("mov.b64 %0, {%1, %2};" : "=l"(r) : "f"(lo), "f"(hi)); return r;
}
__device__ __forceinline__ void unpack2(u64 v, float& lo, float& hi) {
    asm("mov.b64 {%0, %1}, %2;" : "=f"(lo), "=f"(hi) : "l"(v));
}

__device__ __forceinline__ float warpSum(float v) {
    v += __shfl_xor_sync(0xffffffffu, v, 16);
    v += __shfl_xor_sync(0xffffffffu, v, 8);
    v += __shfl_xor_sync(0xffffffffu, v, 4);
    v += __shfl_xor_sync(0xffffffffu, v, 2);
    v += __shfl_xor_sync(0xffffffffu, v, 1);
    return v;
}

// Causal accumulate of (sum, sum*x, sum*y) for row pair (s0 < s1) over an SoA
// array (shared OR global; 8B-aligned). Phase A feeds both rows; phase B
// feeds row1 only. No dead predicated work. All lanes get the reduced sums.
__device__ __forceinline__ void accPair(
    const float* __restrict__ sx, const float* __restrict__ sy,
    int s0, int s1, int lane,
    float rs0x, float rs0y, float rs1x, float rs1y,
    float& A0, float& AX0, float& AY0,
    float& A1, float& AX1, float& AY1)
{
    const u64 rx0 = pack2(rs0x, rs0x), ry0 = pack2(rs0y, rs0y);
    const u64 rx1 = pack2(rs1x, rs1x), ry1 = pack2(rs1y, rs1y);
    u64 a0 = 0, ax0 = 0, ay0 = 0;
    u64 a1 = 0, ax1 = 0, ay1 = 0;

    const int iEndA = s0 >> 1;
    for (int i = lane; i <= iEndA; i += 32) {
        const u64 X = *(const u64*)(sx + 2 * i);
        const u64 Y = *(const u64*)(sy + 2 * i);
        {   // row1: always fully causal in phase A
            u64 d = f2_fma(ry1, Y, f2_mul(rx1, X));
            float dl, dh; unpack2(d, dl, dh);
            dl = fmaxf(dl, 0.f); dh = fmaxf(dh, 0.f);
            u64 v = pack2(dl, dh);
            a1 = f2_add(a1, v); ax1 = f2_fma(v, X, ax1); ay1 = f2_fma(v, Y, ay1);
        }
        {   // row0: guard hi half at the causal edge
            u64 d = f2_fma(ry0, Y, f2_mul(rx0, X));
            float dl, dh; unpack2(d, dl, dh);
            dl = fmaxf(dl, 0.f);
            dh = (2 * i + 1 <= s0) ? fmaxf(dh, 0.f) : 0.f;
            u64 v = pack2(dl, dh);
            a0 = f2_add(a0, v); ax0 = f2_fma(v, X, ax0); ay0 = f2_fma(v, Y, ay0);
        }
    }
    const int iEndB = s1 >> 1;
    for (int i = iEndA + 1 + lane; i <= iEndB; i += 32) {
        const u64 X = *(const u64*)(sx + 2 * i);
        const u64 Y = *(const u64*)(sy + 2 * i);
        u64 d = f2_fma(ry1, Y, f2_mul(rx1, X));
        float dl, dh; unpack2(d, dl, dh);
        dl = fmaxf(dl, 0.f);
        dh = (2 * i + 1 <= s1) ? fmaxf(dh, 0.f) : 0.f;
        u64 v = pack2(dl, dh);
        a1 = f2_add(a1, v); ax1 = f2_fma(v, X, ax1); ay1 = f2_fma(v, Y, ay1);
    }

    float lo, hi;
    unpack2(a0,  lo, hi); A0  = warpSum(lo + hi);
    unpack2(ax0, lo, hi); AX0 = warpSum(lo + hi);
    unpack2(ay0, lo, hi); AY0 = warpSum(lo + hi);
    unpack2(a1,  lo, hi); A1  = warpSum(lo + hi);
    unpack2(ax1, lo, hi); AX1 = warpSum(lo + hi);
    unpack2(ay1, lo, hi); AY1 = warpSum(lo + hi);
}

// One full 4096-float score row from smem SoA. PLAIN write-back float4 stores
// (L2-absorbed; __stcs measured 4.8 TB/s vs ~6.5 TB/s effective for plain).
__device__ __forceinline__ void writeRowS(
    const float* __restrict__ sx, const float* __restrict__ sy,
    int s, float rx, float ry, float inv, float* __restrict__ out, int lane)
{
    const u64 RX = pack2(rx, rx), RY = pack2(ry, ry);
    for (int tb = lane * 4; tb < SS; tb += 128) {
        if (tb > s) {                                     // pure zero tail
            *(float4*)(out + tb) = make_float4(0.f, 0.f, 0.f, 0.f);
            continue;
        }
        const u64 Xa = *(const u64*)(sx + tb), Xb = *(const u64*)(sx + tb + 2);
        const u64 Ya = *(const u64*)(sy + tb), Yb = *(const u64*)(sy + tb + 2);
        u64 dA = f2_fma(RY, Ya, f2_mul(RX, Xa));
        u64 dB = f2_fma(RY, Yb, f2_mul(RX, Xb));
        float w0, w1, w2, w3;
        unpack2(dA, w0, w1); unpack2(dB, w2, w3);
        w0 = fmaxf(w0, 0.f) * inv;
        w1 = fmaxf(w1, 0.f) * inv;
        w2 = fmaxf(w2, 0.f) * inv;
        w3 = fmaxf(w3, 0.f) * inv;
        if (tb + 3 > s) {                                 // causal boundary
            if (tb + 1 > s) w1 = 0.f;
            if (tb + 2 > s) w2 = 0.f;
            if (tb + 3 > s) w3 = 0.f;
        }
        *(float4*)(out + tb) = make_float4(w0, w1, w2, w3);
    }
}

// Pass-1 epilogue for one row: k1, r_mid, inv, rowsum (lane 0 stores).
__device__ __forceinline__ void k1Epilogue(
    int b, int s, float A, float AX, float AY, float rx, float ry, float dtb)
{
    const float inv = 1.0f / fmaxf(A, QEPS);
    float k1x = dtb * (AX * inv); if (!isfinite(k1x)) k1x = 0.f;
    float k1y = dtb * (AY * inv); if (!isfinite(k1y)) k1y = 0.f;
    float rmx = rx + k1x; if (!isfinite(rmx)) rmx = rx;
    float rmy = ry + k1y; if (!isfinite(rmy)) rmy = ry;
    const size_t idx = (size_t)b * SS + s;
    g_rmx[idx] = rmx;  g_rmy[idx] = rmy;
    g_k1x[idx] = k1x;  g_k1y[idx] = k1y;
    g_inv[idx] = inv;  g_rowsum[idx] = A * inv;
}

// ---------------------------------------------------------------------------
// K1: pass-1 accumulate for ALL pairs (2 pairs/warp) + write the score rows of
// its rep-0 pairs (half the 268 MB) with locally-computed inv. Order:
// acc(rep0) -> write 2 rows -> acc(rep1), so stores start issuing early and
// overlap the second accumulate across co-resident blocks.
// ---------------------------------------------------------------------------
__global__ void __launch_bounds__(256)
qi_k1(const float* __restrict__ r, const float* __restrict__ dt,
      float* __restrict__ score)
{
    __shared__ __align__(16) float sx[SS];
    __shared__ __align__(16) float sy[SS];

    const int b    = blockIdx.y;
    const int tid  = threadIdx.x;
    const int warp = tid >> 5, lane = tid & 31;
    const float2* rb = (const float2*)r + (size_t)b * SS;
    float* scoreb = score + (size_t)b * SS * SS;
    const float dtb = dt[b];

    {   // SoA load of r (float4 = 2 points)
        const float4* rb4 = (const float4*)rb;
        for (int i = tid; i < SS / 2; i += 256) {
            float4 v = rb4[i];
            sx[2 * i] = v.x;     sy[2 * i] = v.y;
            sx[2 * i + 1] = v.z; sy[2 * i + 1] = v.w;
        }
    }
    __syncthreads();

    // ---- rep 0 accumulate (pairs this block will also write) ----
    const int p0 = blockIdx.x * 16 + warp;            // [0, 2048) over rep0
    const int s0 = p0, s1 = SS - 1 - p0;
    const float rs0x = sx[s0], rs0y = sy[s0];
    const float rs1x = sx[s1], rs1y = sy[s1];
    float A0, AX0, AY0, A1, AX1, AY1;
    accPair(sx, sy, s0, s1, lane, rs0x, rs0y, rs1x, rs1y,
            A0, AX0, AY0, A1, AX1, AY1);
    const float invA = 1.0f / fmaxf(A0, QEPS);        // all lanes (warpSum bfly)
    const float invB = 1.0f / fmaxf(A1, QEPS);
    if (lane == 0) {
        k1Epilogue(b, s0, A0, AX0, AY0, rs0x, rs0y, dtb);
        k1Epilogue(b, s1, A1, AX1, AY1, rs1x, rs1y, dtb);
    }

    // ---- write this pair's two score rows (DRAM starts now) ----
    writeRowS(sx, sy, s0, rs0x, rs0y, invA, scoreb + (size_t)s0 * SS, lane);
    writeRowS(sx, sy, s1, rs1x, rs1y, invB, scoreb + (size_t)s1 * SS, lane);

    // ---- rep 1 accumulate (rows written by K2) ----
    const int p1 = p0 + 8;
    const int t0 = p1, t1 = SS - 1 - p1;
    const float ts0x = sx[t0], ts0y = sy[t0];
    const float ts1x = sx[t1], ts1y = sy[t1];
    accPair(sx, sy, t0, t1, lane, ts0x, ts0y, ts1x, ts1y,
            A0, AX0, AY0, A1, AX1, AY1);
    if (lane == 0) {
        k1Epilogue(b, t0, A0, AX0, AY0, ts0x, ts0y, dtb);
        k1Epilogue(b, t1, A1, AX1, AY1, ts1x, ts1y, dtb);
    }
}

// ---------------------------------------------------------------------------
// K2: warp-level role mix in EVERY block (no inter-block sync; deps only via
// the K1 kernel boundary).
//   warps 0-5: write the rep-1 pairs' score rows (other half) from smem r.
//   warps 6-7: pass-2 accumulate on r_mid read from GLOBAL (32 KB, L1-hot)
//              + Heun/radius epilogue -> rfinal.
// Every SM hosts writers (DRAM) and compute (issue) simultaneously; the
// pass-2 instruction stream fills the issue slots the store stream leaves.
// ---------------------------------------------------------------------------
__global__ void __launch_bounds__(256)
qi_k2(const float* __restrict__ r, const float* __restrict__ dt,
      float* __restrict__ score, float* __restrict__ rfinal)
{
    __shared__ __align__(16) float sx[SS];
    __shared__ __align__(16) float sy[SS];

    const int b    = blockIdx.y;
    const int bx   = blockIdx.x;              // [0, 128)
    const int tid  = threadIdx.x;
    const int warp = tid >> 5, lane = tid & 31;
    const float2* rb = (const float2*)r + (size_t)b * SS;
    float* scoreb = score + (size_t)b * SS * SS;

    {   // SoA load of r (all 256 threads; uniform sync before role divergence)
        const float4* rb4 = (const float4*)rb;
        for (int i = tid; i < SS / 2; i += 256) {
            float4 v = rb4[i];
            sx[2 * i] = v.x;     sy[2 * i] = v.y;
            sx[2 * i + 1] = v.z; sy[2 * i + 1] = v.w;
        }
    }
    __syncthreads();

    if (warp < 6) {
        // ================= writer warps =================
        // 2048 rep-1 rows per batch over 128*6 = 768 warps (2-3 rows each).
        const int widx = bx * 6 + warp;
        for (int m = widx; m < 2048; m += 768) {
            const int j    = m >> 1;                       // [0, 1024) pair slot
            const int side = m & 1;
            const int p    = ((j >> 3) << 4) + 8 + (j & 7);  // rep-1 pair id
            const int s    = side ? (SS - 1 - p) : p;
            const float inv = g_inv[(size_t)b * SS + s];
            writeRowS(sx, sy, s, sx[s], sy[s], inv,
                      scoreb + (size_t)s * SS, lane);
        }
    } else {
        // ================= compute warps =================
        const float dtb = dt[b];
        const float* gx = g_rmx + (size_t)b * SS;          // 16B-aligned base
        const float* gy = g_rmy + (size_t)b * SS;
        const int cidx = bx * 2 + (warp - 6);              // [0, 256)
        for (int q = cidx; q < 2048; q += 256) {           // 8 pairs per warp
            const int s0 = q, s1 = SS - 1 - q;
            const float m0x = __ldg(gx + s0), m0y = __ldg(gy + s0);
            const float m1x = __ldg(gx + s1), m1y = __ldg(gy + s1);
            float A0, AX0, AY0, A1, AX1, AY1;
            accPair(gx, gy, s0, s1, lane, m0x, m0y, m1x, m1y,
                    A0, AX0, AY0, A1, AX1, AY1);
            if (lane == 0) {
#pragma unroll
                for (int w = 0; w < 2; w++) {
                    const int   s  = w ? s1 : s0;
                    const float A  = w ? A1 : A0;
                    const float AX = w ? AX1 : AX0;
                    const float AY = w ? AY1 : AY0;
                    const size_t idx = (size_t)b * SS + s;
                    const float inv = 1.0f / fmaxf(A, QEPS);
                    float k2x = dtb * (AX * inv); if (!isfinite(k2x)) k2x = 0.f;
                    float k2y = dtb * (AY * inv); if (!isfinite(k2y)) k2y = 0.f;
                    const float2 r0 = rb[s];
                    float rnx = r0.x + 0.5f * (g_k1x[idx] + k2x);
                    float rny = r0.y + 0.5f * (g_k1y[idx] + k2y);
                    float nr  = fmaxf(sqrtf(rnx * rnx + rny * rny), QEPS);
                    float ar  = fminf(fmaxf(nr + g_rowsum[idx] * 0.01f, 0.1f), 2.0f);
                    float sc  = ar / nr;
                    float fx = rnx * sc; if (!isfinite(fx)) fx = r0.x;
                    float fy = rny * sc; if (!isfinite(fy)) fy = r0.y;
                    ((float2*)rfinal)[idx] = make_float2(fx, fy);
                }
            }
        }
    }
}

extern "C" void kernel_launch(void* const* d_in, const int* in_sizes, int n_in,
                              void* d_out, int out_size) {
    const float* r  = (const float*)d_in[0];
    const float* dt = (const float*)d_in[1];
    if (in_sizes[0] == BB && in_sizes[1] == BB * SS * 2) {
        r  = (const float*)d_in[1];
        dt = (const float*)d_in[0];
    }
    float* out    = (float*)d_out;
    float* rfinal = out;                          // [B,S,2]
    float* score  = out + (size_t)BB * SS * 2;    // [B,S,S]

    qi_k1<<<dim3(128, BB), 256>>>(r, dt, score);           // acc all + half writes
    qi_k2<<<dim3(128, BB), 256>>>(r, dt, score, rfinal);   // half writes + pass-2
}

// round 15
// speedup vs baseline: 1.8068x; 1.8068x over previous
#include <cuda_runtime.h>
#include <math.h>

#define BB   4
#define SS   4096
#define QEPS 1e-6f

typedef unsigned long long u64;

// ---- scratch (no allocation allowed): K1 -> K2 hand-off ----
__device__ __align__(16) float g_rmx[BB * SS];
__device__ __align__(16) float g_rmy[BB * SS];
__device__ __align__(16) float g_k1x[BB * SS];
__device__ __align__(16) float g_k1y[BB * SS];
__device__ __align__(16) float g_inv[BB * SS];
__device__ __align__(16) float g_rowsum[BB * SS];

// ---- packed fp32x2 helpers (Blackwell FFMA2 pipe, PTX-only) ----
__device__ __forceinline__ u64 f2_mul(u64 a, u64 b) {
    u64 r; asm("mul.rn.f32x2 %0, %1, %2;" : "=l"(r) : "l"(a), "l"(b)); return r;
}
__device__ __forceinline__ u64 f2_fma(u64 a, u64 b, u64 c) {
    u64 r; asm("fma.rn.f32x2 %0, %1, %2, %3;" : "=l"(r) : "l"(a), "l"(b), "l"(c)); return r;
}
__device__ __forceinline__ u64 f2_add(u64 a, u64 b) {
    u64 r; asm("add.rn.f32x2 %0, %1, %2;" : "=l"(r) : "l"(a), "l"(b)); return r;
}
__device__ __forceinline__ u64 pack2(float lo, float hi) {
    u64 r; asm("mov.b64 %0, {%1, %2};" : "=l"(r) : "f"(lo), "f"(hi)); return r;
}
__device__ __forceinline__ void unpack2(u64 v, float& lo, float& hi) {
    asm("mov.b64 {%0, %1}, %2;" : "=f"(lo), "=f"(hi) : "l"(v));
}

__device__ __forceinline__ float warpSum(float v) {
    v += __shfl_xor_sync(0xffffffffu, v, 16);
    v += __shfl_xor_sync(0xffffffffu, v, 8);
    v += __shfl_xor_sync(0xffffffffu, v, 4);
    v += __shfl_xor_sync(0xffffffffu, v, 2);
    v += __shfl_xor_sync(0xffffffffu, v, 1);
    return v;
}

// Causal accumulate of (sum, sum*x, sum*y) for row pair (s0 < s1) over SoA
// SHARED-memory arrays. Phase A feeds both rows; phase B feeds row1 only.
// All lanes receive the reduced sums (butterfly).
__device__ __forceinline__ void accPair(
    const float* __restrict__ sx, const float* __restrict__ sy,
    int s0, int s1, int lane,
    float rs0x, float rs0y, float rs1x, float rs1y,
    float& A0, float& AX0, float& AY0,
    float& A1, float& AX1, float& AY1)
{
    const u64 rx0 = pack2(rs0x, rs0x), ry0 = pack2(rs0y, rs0y);
    const u64 rx1 = pack2(rs1x, rs1x), ry1 = pack2(rs1y, rs1y);
    u64 a0 = 0, ax0 = 0, ay0 = 0;
    u64 a1 = 0, ax1 = 0, ay1 = 0;

    const int iEndA = s0 >> 1;
    for (int i = lane; i <= iEndA; i += 32) {
        const u64 X = *(const u64*)(sx + 2 * i);
        const u64 Y = *(const u64*)(sy + 2 * i);
        {   // row1: always fully causal in phase A
            u64 d = f2_fma(ry1, Y, f2_mul(rx1, X));
            float dl, dh; unpack2(d, dl, dh);
            dl = fmaxf(dl, 0.f); dh = fmaxf(dh, 0.f);
            u64 v = pack2(dl, dh);
            a1 = f2_add(a1, v); ax1 = f2_fma(v, X, ax1); ay1 = f2_fma(v, Y, ay1);
        }
        {   // row0: guard hi half at the causal edge
            u64 d = f2_fma(ry0, Y, f2_mul(rx0, X));
            float dl, dh; unpack2(d, dl, dh);
            dl = fmaxf(dl, 0.f);
            dh = (2 * i + 1 <= s0) ? fmaxf(dh, 0.f) : 0.f;
            u64 v = pack2(dl, dh);
            a0 = f2_add(a0, v); ax0 = f2_fma(v, X, ax0); ay0 = f2_fma(v, Y, ay0);
        }
    }
    const int iEndB = s1 >> 1;
    for (int i = iEndA + 1 + lane; i <= iEndB; i += 32) {
        const u64 X = *(const u64*)(sx + 2 * i);
        const u64 Y = *(const u64*)(sy + 2 * i);
        u64 d = f2_fma(ry1, Y, f2_mul(rx1, X));
        float dl, dh; unpack2(d, dl, dh);
        dl = fmaxf(dl, 0.f);
        dh = (2 * i + 1 <= s1) ? fmaxf(dh, 0.f) : 0.f;
        u64 v = pack2(dl, dh);
        a1 = f2_add(a1, v); ax1 = f2_fma(v, X, ax1); ay1 = f2_fma(v, Y, ay1);
    }

    float lo, hi;
    unpack2(a0,  lo, hi); A0  = warpSum(lo + hi);
    unpack2(ax0, lo, hi); AX0 = warpSum(lo + hi);
    unpack2(ay0, lo, hi); AY0 = warpSum(lo + hi);
    unpack2(a1,  lo, hi); A1  = warpSum(lo + hi);
    unpack2(ax1, lo, hi); AX1 = warpSum(lo + hi);
    unpack2(ay1, lo, hi); AY1 = warpSum(lo + hi);
}

// One full 4096-float score row from smem SoA, streaming float4 stores.
// (This exact path measured 26us for acc+half-writes in the R10 K1 context.)
__device__ __forceinline__ void writeRowS(
    const float* __restrict__ sx, const float* __restrict__ sy,
    int s, float rx, float ry, float inv, float* __restrict__ out, int lane)
{
    const u64 RX = pack2(rx, rx), RY = pack2(ry, ry);
    for (int tb = lane * 4; tb < SS; tb += 128) {
        if (tb > s) {                                     // pure zero tail
            __stcs((float4*)(out + tb), make_float4(0.f, 0.f, 0.f, 0.f));
            continue;
        }
        const u64 Xa = *(const u64*)(sx + tb), Xb = *(const u64*)(sx + tb + 2);
        const u64 Ya = *(const u64*)(sy + tb), Yb = *(const u64*)(sy + tb + 2);
        u64 dA = f2_fma(RY, Ya, f2_mul(RX, Xa));
        u64 dB = f2_fma(RY, Yb, f2_mul(RX, Xb));
        float w0, w1, w2, w3;
        unpack2(dA, w0, w1); unpack2(dB, w2, w3);
        w0 = fmaxf(w0, 0.f) * inv;
        w1 = fmaxf(w1, 0.f) * inv;
        w2 = fmaxf(w2, 0.f) * inv;
        w3 = fmaxf(w3, 0.f) * inv;
        if (tb + 3 > s) {                                 // causal boundary
            if (tb + 1 > s) w1 = 0.f;
            if (tb + 2 > s) w2 = 0.f;
            if (tb + 3 > s) w3 = 0.f;
        }
        __stcs((float4*)(out + tb), make_float4(w0, w1, w2, w3));
    }
}

// ---------------------------------------------------------------------------
// K1 (== R10's 26us kernel): pass-1 accumulate for all pairs (1 pair/warp,
// 256 blocks/batch) + write the score rows of EVEN-local pairs (half of 268MB)
// smem-fed. Blocks desync, so stores overlap accumulates chip-wide.
// ---------------------------------------------------------------------------
__global__ void __launch_bounds__(256)
qi_k1(const float* __restrict__ r, const float* __restrict__ dt,
      float* __restrict__ score)
{
    __shared__ __align__(16) float sx[SS];
    __shared__ __align__(16) float sy[SS];
    __shared__ float sInv[16];

    const int b     = blockIdx.y;
    const int tid   = threadIdx.x;
    const int warp  = tid >> 5, lane = tid & 31;
    const int bbase = blockIdx.x * 8;
    const float2* rb = (const float2*)r + (size_t)b * SS;
    const float dtb = dt[b];

    {   // SoA load of r (float4 = 2 points)
        const float4* rb4 = (const float4*)rb;
        for (int i = tid; i < SS / 2; i += 256) {
            float4 v = rb4[i];
            sx[2 * i] = v.x;     sy[2 * i] = v.y;
            sx[2 * i + 1] = v.z; sy[2 * i + 1] = v.w;
        }
    }
    __syncthreads();

    const int s0 = bbase + warp, s1 = SS - 1 - s0;
    const float rs0x = sx[s0], rs0y = sy[s0];
    const float rs1x = sx[s1], rs1y = sy[s1];
    float A0, AX0, AY0, A1, AX1, AY1;
    accPair(sx, sy, s0, s1, lane, rs0x, rs0y, rs1x, rs1y,
            A0, AX0, AY0, A1, AX1, AY1);

    if (lane == 0) {
#pragma unroll
        for (int w = 0; w < 2; w++) {
            const int   s  = w ? s1 : s0;
            const float A  = w ? A1 : A0;
            const float AX = w ? AX1 : AX0;
            const float AY = w ? AY1 : AY0;
            const float rx = w ? rs1x : rs0x;
            const float ry = w ? rs1y : rs0y;
            const float inv = 1.0f / fmaxf(A, QEPS);
            float k1x = dtb * (AX * inv); if (!isfinite(k1x)) k1x = 0.f;
            float k1y = dtb * (AY * inv); if (!isfinite(k1y)) k1y = 0.f;
            float rmx = rx + k1x; if (!isfinite(rmx)) rmx = rx;
            float rmy = ry + k1y; if (!isfinite(rmy)) rmy = ry;
            const size_t idx = (size_t)b * SS + s;
            g_rmx[idx] = rmx;  g_rmy[idx] = rmy;
            g_k1x[idx] = k1x;  g_k1y[idx] = k1y;
            g_inv[idx] = inv;  g_rowsum[idx] = A * inv;
            sInv[2 * warp + w] = inv;
        }
    }
    __syncthreads();

    // Write rows of pairs with even local index i in {0,2,4,6}: 8 rows, 1/warp.
    const int i   = (warp >> 1) << 1;
    const int pp  = bbase + i;
    const int row = (warp & 1) ? (SS - 1 - pp) : pp;
    const float inv = sInv[2 * i + (warp & 1)];
    writeRowS(sx, sy, row, sx[row], sy[row], inv,
              score + ((size_t)b * SS + row) * SS, lane);
}

// ---------------------------------------------------------------------------
// K2: block-level role split, 256 blocks/batch, roles interleaved by bx&1 so
// every SM hosts both. NO inter-block sync (deps only via kernel boundary).
//   bx even -> writer: odd-local-pair score rows (other 134MB), smem-fed from r
//   bx odd  -> compute: pass-2 accumulate on r_mid in SMEM (coalesced SoA
//              load from global scratch) + Heun/radius epilogue -> rfinal
// ---------------------------------------------------------------------------
__global__ void __launch_bounds__(256)
qi_k2(const float* __restrict__ r, const float* __restrict__ dt,
      float* __restrict__ score, float* __restrict__ rfinal)
{
    __shared__ __align__(16) float sx[SS];
    __shared__ __align__(16) float sy[SS];

    const int b    = blockIdx.y;
    const int bx   = blockIdx.x;              // [0, 256)
    const int tid  = threadIdx.x;
    const int warp = tid >> 5, lane = tid & 31;
    const int half = bx >> 1;                 // [0, 128)
    const float2* rb = (const float2*)r + (size_t)b * SS;
    float* scoreb = score + (size_t)b * SS * SS;

    if ((bx & 1) == 0) {
        // ================= writer role =================
        {   // SoA load of r
            const float4* rb4 = (const float4*)rb;
            for (int i = tid; i < SS / 2; i += 256) {
                float4 v = rb4[i];
                sx[2 * i] = v.x;     sy[2 * i] = v.y;
                sx[2 * i + 1] = v.z; sy[2 * i + 1] = v.w;
            }
        }
        __syncthreads();

        // 2048 odd-local rows total; this block: 16, this warp: 2.
#pragma unroll
        for (int k = 0; k < 2; k++) {
            const int flat = half * 16 + warp * 2 + k;    // [0, 2048)
            const int g    = flat >> 3;                   // pair group [0,256)
            const int rem  = flat & 7;
            const int p    = g * 8 + 2 * (rem >> 1) + 1;  // odd local pair
            const int s    = (rem & 1) ? (SS - 1 - p) : p;
            const float inv = g_inv[(size_t)b * SS + s];
            writeRowS(sx, sy, s, sx[s], sy[s], inv,
                      scoreb + (size_t)s * SS, lane);
        }
    } else {
        // ================= compute role =================
        const float dtb = dt[b];
        {   // SoA load of r_mid (already SoA in global -> coalesced float4)
            const float4* gx4 = (const float4*)(g_rmx + (size_t)b * SS);
            const float4* gy4 = (const float4*)(g_rmy + (size_t)b * SS);
            for (int i = tid; i < SS / 4; i += 256) {
                *(float4*)(sx + 4 * i) = gx4[i];
                *(float4*)(sy + 4 * i) = gy4[i];
            }
        }
        __syncthreads();

#pragma unroll
        for (int rep = 0; rep < 2; rep++) {
            const int q  = half * 16 + warp * 2 + rep;    // [0, 2048)
            const int s0 = q, s1 = SS - 1 - q;
            const float m0x = sx[s0], m0y = sy[s0];
            const float m1x = sx[s1], m1y = sy[s1];
            float A0, AX0, AY0, A1, AX1, AY1;
            accPair(sx, sy, s0, s1, lane, m0x, m0y, m1x, m1y,
                    A0, AX0, AY0, A1, AX1, AY1);
            if (lane == 0) {
#pragma unroll
                for (int w = 0; w < 2; w++) {
                    const int   s  = w ? s1 : s0;
                    const float A  = w ? A1 : A0;
                    const float AX = w ? AX1 : AX0;
                    const float AY = w ? AY1 : AY0;
                    const size_t idx = (size_t)b * SS + s;
                    const float inv = 1.0f / fmaxf(A, QEPS);
                    float k2x = dtb * (AX * inv); if (!isfinite(k2x)) k2x = 0.f;
                    float k2y = dtb * (AY * inv); if (!isfinite(k2y)) k2y = 0.f;
                    const float2 r0 = __ldg(rb + s);
                    float rnx = r0.x + 0.5f * (g_k1x[idx] + k2x);
                    float rny = r0.y + 0.5f * (g_k1y[idx] + k2y);
                    float nr  = fmaxf(sqrtf(rnx * rnx + rny * rny), QEPS);
                    float ar  = fminf(fmaxf(nr + g_rowsum[idx] * 0.01f, 0.1f), 2.0f);
                    float sc  = ar / nr;
                    float fx = rnx * sc; if (!isfinite(fx)) fx = r0.x;
                    float fy = rny * sc; if (!isfinite(fy)) fy = r0.y;
                    ((float2*)rfinal)[idx] = make_float2(fx, fy);
                }
            }
        }
    }
}

extern "C" void kernel_launch(void* const* d_in, const int* in_sizes, int n_in,
                              void* d_out, int out_size) {
    const float* r  = (const float*)d_in[0];
    const float* dt = (const float*)d_in[1];
    if (in_sizes[0] == BB && in_sizes[1] == BB * SS * 2) {
        r  = (const float*)d_in[1];
        dt = (const float*)d_in[0];
    }
    float* out    = (float*)d_out;
    float* rfinal = out;                          // [B,S,2]
    float* score  = out + (size_t)BB * SS * 2;    // [B,S,S]

    qi_k1<<<dim3(256, BB), 256>>>(r, dt, score);           // acc all + even rows
    qi_k2<<<dim3(256, BB), 256>>>(r, dt, score, rfinal);   // odd rows + pass-2
}

// round 17
// speedup vs baseline: 1.8240x; 1.0095x over previous
#include <cuda_runtime.h>
#include <math.h>

#define BB   4
#define SS   4096
#define QEPS 1e-6f

typedef unsigned long long u64;

// ---- scratch (no allocation allowed): K1 -> K2 hand-off ----
__device__ __align__(16) float g_rmx[BB * SS];
__device__ __align__(16) float g_rmy[BB * SS];
__device__ __align__(16) float g_k1x[BB * SS];
__device__ __align__(16) float g_k1y[BB * SS];
__device__ __align__(16) float g_inv[BB * SS];
__device__ __align__(16) float g_rowsum[BB * SS];

// ---- packed fp32x2 helpers (Blackwell FFMA2 pipe, PTX-only) ----
__device__ __forceinline__ u64 f2_mul(u64 a, u64 b) {
    u64 r; asm("mul.rn.f32x2 %0, %1, %2;" : "=l"(r) : "l"(a), "l"(b)); return r;
}
__device__ __forceinline__ u64 f2_fma(u64 a, u64 b, u64 c) {
    u64 r; asm("fma.rn.f32x2 %0, %1, %2, %3;" : "=l"(r) : "l"(a), "l"(b), "l"(c)); return r;
}
__device__ __forceinline__ u64 f2_add(u64 a, u64 b) {
    u64 r; asm("add.rn.f32x2 %0, %1, %2;" : "=l"(r) : "l"(a), "l"(b)); return r;
}
__device__ __forceinline__ u64 pack2(float lo, float hi) {
    u64 r; asm("mov.b64 %0, {%1, %2};" : "=l"(r) : "f"(lo), "f"(hi)); return r;
}
__device__ __forceinline__ void unpack2(u64 v, float& lo, float& hi) {
    asm("mov.b64 {%0, %1}, %2;" : "=f"(lo), "=f"(hi) : "l"(v));
}

__device__ __forceinline__ float warpSum(float v) {
    v += __shfl_xor_sync(0xffffffffu, v, 16);
    v += __shfl_xor_sync(0xffffffffu, v, 8);
    v += __shfl_xor_sync(0xffffffffu, v, 4);
    v += __shfl_xor_sync(0xffffffffu, v, 2);
    v += __shfl_xor_sync(0xffffffffu, v, 1);
    return v;
}

// Causal accumulate of (sum, sum*x, sum*y) for row pair (s0 < s1) over SoA
// SHARED-memory arrays. Phase A feeds both rows; phase B feeds row1 only.
// All lanes receive the reduced sums (butterfly).
__device__ __forceinline__ void accPair(
    const float* __restrict__ sx, const float* __restrict__ sy,
    int s0, int s1, int lane,
    float rs0x, float rs0y, float rs1x, float rs1y,
    float& A0, float& AX0, float& AY0,
    float& A1, float& AX1, float& AY1)
{
    const u64 rx0 = pack2(rs0x, rs0x), ry0 = pack2(rs0y, rs0y);
    const u64 rx1 = pack2(rs1x, rs1x), ry1 = pack2(rs1y, rs1y);
    u64 a0 = 0, ax0 = 0, ay0 = 0;
    u64 a1 = 0, ax1 = 0, ay1 = 0;

    const int iEndA = s0 >> 1;
    for (int i = lane; i <= iEndA; i += 32) {
        const u64 X = *(const u64*)(sx + 2 * i);
        const u64 Y = *(const u64*)(sy + 2 * i);
        {   // row1: always fully causal in phase A
            u64 d = f2_fma(ry1, Y, f2_mul(rx1, X));
            float dl, dh; unpack2(d, dl, dh);
            dl = fmaxf(dl, 0.f); dh = fmaxf(dh, 0.f);
            u64 v = pack2(dl, dh);
            a1 = f2_add(a1, v); ax1 = f2_fma(v, X, ax1); ay1 = f2_fma(v, Y, ay1);
        }
        {   // row0: guard hi half at the causal edge
            u64 d = f2_fma(ry0, Y, f2_mul(rx0, X));
            float dl, dh; unpack2(d, dl, dh);
            dl = fmaxf(dl, 0.f);
            dh = (2 * i + 1 <= s0) ? fmaxf(dh, 0.f) : 0.f;
            u64 v = pack2(dl, dh);
            a0 = f2_add(a0, v); ax0 = f2_fma(v, X, ax0); ay0 = f2_fma(v, Y, ay0);
        }
    }
    const int iEndB = s1 >> 1;
    for (int i = iEndA + 1 + lane; i <= iEndB; i += 32) {
        const u64 X = *(const u64*)(sx + 2 * i);
        const u64 Y = *(const u64*)(sy + 2 * i);
        u64 d = f2_fma(ry1, Y, f2_mul(rx1, X));
        float dl, dh; unpack2(d, dl, dh);
        dl = fmaxf(dl, 0.f);
        dh = (2 * i + 1 <= s1) ? fmaxf(dh, 0.f) : 0.f;
        u64 v = pack2(dl, dh);
        a1 = f2_add(a1, v); ax1 = f2_fma(v, X, ax1); ay1 = f2_fma(v, Y, ay1);
    }

    float lo, hi;
    unpack2(a0,  lo, hi); A0  = warpSum(lo + hi);
    unpack2(ax0, lo, hi); AX0 = warpSum(lo + hi);
    unpack2(ay0, lo, hi); AY0 = warpSum(lo + hi);
    unpack2(a1,  lo, hi); A1  = warpSum(lo + hi);
    unpack2(ax1, lo, hi); AX1 = warpSum(lo + hi);
    unpack2(ay1, lo, hi); AY1 = warpSum(lo + hi);
}

// One full 4096-float score row from smem SoA, streaming float4 stores.
__device__ __forceinline__ void writeRowS(
    const float* __restrict__ sx, const float* __restrict__ sy,
    int s, float rx, float ry, float inv, float* __restrict__ out, int lane)
{
    const u64 RX = pack2(rx, rx), RY = pack2(ry, ry);
    for (int tb = lane * 4; tb < SS; tb += 128) {
        if (tb > s) {                                     // pure zero tail
            __stcs((float4*)(out + tb), make_float4(0.f, 0.f, 0.f, 0.f));
            continue;
        }
        const u64 Xa = *(const u64*)(sx + tb), Xb = *(const u64*)(sx + tb + 2);
        const u64 Ya = *(const u64*)(sy + tb), Yb = *(const u64*)(sy + tb + 2);
        u64 dA = f2_fma(RY, Ya, f2_mul(RX, Xa));
        u64 dB = f2_fma(RY, Yb, f2_mul(RX, Xb));
        float w0, w1, w2, w3;
        unpack2(dA, w0, w1); unpack2(dB, w2, w3);
        w0 = fmaxf(w0, 0.f) * inv;
        w1 = fmaxf(w1, 0.f) * inv;
        w2 = fmaxf(w2, 0.f) * inv;
        w3 = fmaxf(w3, 0.f) * inv;
        if (tb + 3 > s) {                                 // causal boundary
            if (tb + 1 > s) w1 = 0.f;
            if (tb + 2 > s) w2 = 0.f;
            if (tb + 3 > s) w3 = 0.f;
        }
        __stcs((float4*)(out + tb), make_float4(w0, w1, w2, w3));
    }
}

// ---------------------------------------------------------------------------
// K1 (twice-measured ~26us): pass-1 accumulate for all pairs (1 pair/warp,
// 256 blocks/batch) + write the score rows of EVEN pairs (half of 268MB).
// ---------------------------------------------------------------------------
__global__ void __launch_bounds__(256)
qi_k1(const float* __restrict__ r, const float* __restrict__ dt,
      float* __restrict__ score)
{
    __shared__ __align__(16) float sx[SS];
    __shared__ __align__(16) float sy[SS];
    __shared__ float sInv[16];

    const int b     = blockIdx.y;
    const int tid   = threadIdx.x;
    const int warp  = tid >> 5, lane = tid & 31;
    const int bbase = blockIdx.x * 8;
    const float2* rb = (const float2*)r + (size_t)b * SS;
    const float dtb = dt[b];

    {   // SoA load of r (float4 = 2 points)
        const float4* rb4 = (const float4*)rb;
        for (int i = tid; i < SS / 2; i += 256) {
            float4 v = rb4[i];
            sx[2 * i] = v.x;     sy[2 * i] = v.y;
            sx[2 * i + 1] = v.z; sy[2 * i + 1] = v.w;
        }
    }
    __syncthreads();

    const int s0 = bbase + warp, s1 = SS - 1 - s0;
    const float rs0x = sx[s0], rs0y = sy[s0];
    const float rs1x = sx[s1], rs1y = sy[s1];
    float A0, AX0, AY0, A1, AX1, AY1;
    accPair(sx, sy, s0, s1, lane, rs0x, rs0y, rs1x, rs1y,
            A0, AX0, AY0, A1, AX1, AY1);

    if (lane == 0) {
#pragma unroll
        for (int w = 0; w < 2; w++) {
            const int   s  = w ? s1 : s0;
            const float A  = w ? A1 : A0;
            const float AX = w ? AX1 : AX0;
            const float AY = w ? AY1 : AY0;
            const float rx = w ? rs1x : rs0x;
            const float ry = w ? rs1y : rs0y;
            const float inv = 1.0f / fmaxf(A, QEPS);
            float k1x = dtb * (AX * inv); if (!isfinite(k1x)) k1x = 0.f;
            float k1y = dtb * (AY * inv); if (!isfinite(k1y)) k1y = 0.f;
            float rmx = rx + k1x; if (!isfinite(rmx)) rmx = rx;
            float rmy = ry + k1y; if (!isfinite(rmy)) rmy = ry;
            const size_t idx = (size_t)b * SS + s;
            g_rmx[idx] = rmx;  g_rmy[idx] = rmy;
            g_k1x[idx] = k1x;  g_k1y[idx] = k1y;
            g_inv[idx] = inv;  g_rowsum[idx] = A * inv;
            sInv[2 * warp + w] = inv;
        }
    }
    __syncthreads();

    // Write rows of pairs with even local index i in {0,2,4,6}: 8 rows, 1/warp.
    const int i   = (warp >> 1) << 1;
    const int pp  = bbase + i;
    const int row = (warp & 1) ? (SS - 1 - pp) : pp;
    const float inv = sInv[2 * i + (warp & 1)];
    writeRowS(sx, sy, row, sx[row], sy[row], inv,
              score + ((size_t)b * SS + row) * SS, lane);
}

// ---------------------------------------------------------------------------
// K2: UNIFORM blocks, two phases each, order staggered by bx%3 (3 does not
// divide 148, so the phase mix rotates across SMs — every SM stores while
// pass-2 runs somewhere on it). No inter-block sync; deps via K1 boundary.
//   Phase W: smem <- r;     write this block's 8 ODD-pair score rows (g_inv)
//   Phase A: smem <- r_mid; pass-2 accumulate 8 pairs (1/warp) + rfinal
// bx%3 != 0 -> W first (2/3 of blocks feed DRAM from t=0); bx%3 == 0 -> A first.
// The phase branch is block-uniform, so every __syncthreads is uniform.
// ---------------------------------------------------------------------------
__global__ void __launch_bounds__(256)
qi_k2(const float* __restrict__ r, const float* __restrict__ dt,
      float* __restrict__ score, float* __restrict__ rfinal)
{
    __shared__ __align__(16) float sx[SS];
    __shared__ __align__(16) float sy[SS];

    const int b    = blockIdx.y;
    const int bx   = blockIdx.x;              // [0, 256)
    const int tid  = threadIdx.x;
    const int warp = tid >> 5, lane = tid & 31;
    const float2* rb = (const float2*)r + (size_t)b * SS;
    float* scoreb = score + (size_t)b * SS * SS;
    const float dtb = dt[b];
    const bool writeFirst = (bx % 3) != 0;

#pragma unroll 1
    for (int phase = 0; phase < 2; phase++) {
        const bool doWrite = (phase == 0) == writeFirst;
        if (doWrite) {
            // ---- Phase W: load r, write 8 odd-pair rows ----
            const float4* rb4 = (const float4*)rb;
            for (int i = tid; i < SS / 2; i += 256) {
                float4 v = rb4[i];
                sx[2 * i] = v.x;     sy[2 * i] = v.y;
                sx[2 * i + 1] = v.z; sy[2 * i + 1] = v.w;
            }
            __syncthreads();
            const int p = bx * 8 + 2 * (warp >> 1) + 1;   // odd local pair
            const int s = (warp & 1) ? (SS - 1 - p) : p;
            const float inv = g_inv[(size_t)b * SS + s];
            writeRowS(sx, sy, s, sx[s], sy[s], inv,
                      scoreb + (size_t)s * SS, lane);
            __syncthreads();   // all warps done reading smem before reload
        } else {
            // ---- Phase A: load r_mid, pass-2 accumulate 8 pairs ----
            const float4* gx4 = (const float4*)(g_rmx + (size_t)b * SS);
            const float4* gy4 = (const float4*)(g_rmy + (size_t)b * SS);
            for (int i = tid; i < SS / 4; i += 256) {
                *(float4*)(sx + 4 * i) = gx4[i];
                *(float4*)(sy + 4 * i) = gy4[i];
            }
            __syncthreads();
            const int q  = bx * 8 + warp;                 // [0, 2048)
            const int s0 = q, s1 = SS - 1 - q;
            const float m0x = sx[s0], m0y = sy[s0];
            const float m1x = sx[s1], m1y = sy[s1];
            float A0, AX0, AY0, A1, AX1, AY1;
            accPair(sx, sy, s0, s1, lane, m0x, m0y, m1x, m1y,
                    A0, AX0, AY0, A1, AX1, AY1);
            if (lane == 0) {
#pragma unroll
                for (int w = 0; w < 2; w++) {
                    const int   s  = w ? s1 : s0;
                    const float A  = w ? A1 : A0;
                    const float AX = w ? AX1 : AX0;
                    const float AY = w ? AY1 : AY0;
                    const size_t idx = (size_t)b * SS + s;
                    const float inv = 1.0f / fmaxf(A, QEPS);
                    float k2x = dtb * (AX * inv); if (!isfinite(k2x)) k2x = 0.f;
                    float k2y = dtb * (AY * inv); if (!isfinite(k2y)) k2y = 0.f;
                    const float2 r0 = __ldg(rb + s);
                    float rnx = r0.x + 0.5f * (g_k1x[idx] + k2x);
                    float rny = r0.y + 0.5f * (g_k1y[idx] + k2y);
                    float nr  = fmaxf(sqrtf(rnx * rnx + rny * rny), QEPS);
                    float ar  = fminf(fmaxf(nr + g_rowsum[idx] * 0.01f, 0.1f), 2.0f);
                    float sc  = ar / nr;
                    float fx = rnx * sc; if (!isfinite(fx)) fx = r0.x;
                    float fy = rny * sc; if (!isfinite(fy)) fy = r0.y;
                    ((float2*)rfinal)[idx] = make_float2(fx, fy);
                }
            }
            __syncthreads();   // all warps done reading smem before reload
        }
    }
}

extern "C" void kernel_launch(void* const* d_in, const int* in_sizes, int n_in,
                              void* d_out, int out_size) {
    const float* r  = (const float*)d_in[0];
    const float* dt = (const float*)d_in[1];
    if (in_sizes[0] == BB && in_sizes[1] == BB * SS * 2) {
        r  = (const float*)d_in[1];
        dt = (const float*)d_in[0];
    }
    float* out    = (float*)d_out;
    float* rfinal = out;                          // [B,S,2]
    float* score  = out + (size_t)BB * SS * 2;    // [B,S,S]

    qi_k1<<<dim3(256, BB), 256>>>(r, dt, score);           // acc all + even rows
    qi_k2<<<dim3(256, BB), 256>>>(r, dt, score, rfinal);   // odd rows + pass-2
}